// round 13
// baseline (speedup 1.0000x reference)
#include <cuda_runtime.h>
#include <math.h>

#define BLOCK_THREADS 128
#define DIRS_PER_THREAD 2
#define DIRS_PER_BLOCK (BLOCK_THREADS * DIRS_PER_THREAD)
#define MAX_COMP 64

__device__ __forceinline__ float ex2a(float x) {
    float r; asm("ex2.approx.ftz.f32 %0, %1;" : "=f"(r) : "f"(x)); return r;
}

__global__ void __launch_bounds__(BLOCK_THREADS, 16)
vmf_mixture_kernel(const float* __restrict__ lambdas,
                   const float* __restrict__ kappas,
                   const float* __restrict__ thetas,
                   const float* __restrict__ phis,
                   const float* __restrict__ wi,
                   float* __restrict__ out,
                   int S, int N)
{
    // per component: {ax, ay, az, b} with a = kappa*log2e folded into mu,
    // b = log2(lambda*norm) - a  (weight folded into the exponent)
    __shared__ float4 sC[MAX_COMP];

    int t = threadIdx.x;
    if (t < N) {
        float kappa = kappas[t];
        float lam   = lambdas[t];
        float th    = thetas[t];
        float ph    = phis[t];

        float st = sinf(th), ct = cosf(th);
        float sp = sinf(ph), cp = cosf(ph);

        float k = fmaxf(kappa, 1e-8f);
        float norm = (kappa < 1e-5f)
                   ? 0.07957747154594767f                       // 1/(4pi)
                   : k * 0.15915494309189535f / (1.0f - expf(-2.0f * k));
        float c = lam * norm;                                   // > 0 always

        const float LOG2E = 1.4426950408889634f;
        float a = kappa * LOG2E;
        float b = log2f(c) - a;
        sC[t] = make_float4(a * (st * cp), a * (st * sp), a * ct, b);
    }
    __syncthreads();

    // contiguous pair of directions per thread: 3x LDG.64 in, 1x STG.64 out
    int gid = blockIdx.x * BLOCK_THREADS + t;          // pair index
    int i0 = 2 * gid;
    int i1 = i0 + 1;
    bool ok0 = (i0 < S);
    bool ok1 = (i1 < S);
    long long off = ok0 ? (long long)3 * i0 : 0;       // 6 consecutive floats

    const float2* wv = (const float2*)(wi + off);      // 8B-aligned (24B stride)
    float2 p0 = wv[0];                                 // x0 y0
    float2 p1 = wv[1];                                 // z0 x1
    float2 p2 = wv[2];                                 // y1 z1
    float x0 = p0.x, y0 = p0.y, z0 = p1.x;
    float x1 = p1.y, y1 = p2.x, z1 = p2.y;

    float acc0 = 0.0f, acc1 = 0.0f;

    if (N == MAX_COMP) {
        // compile-time trip count: fully unrolled, globally scheduled
        #pragma unroll
        for (int n = 0; n < MAX_COMP; n++) {
            float4 c = sC[n];
            float a0 = fmaf(c.x, x0, fmaf(c.y, y0, fmaf(c.z, z0, c.w)));
            float a1 = fmaf(c.x, x1, fmaf(c.y, y1, fmaf(c.z, z1, c.w)));
            acc0 += ex2a(a0);
            acc1 += ex2a(a1);
        }
    } else {
        #pragma unroll 4
        for (int n = 0; n < N; n++) {
            float4 c = sC[n];
            float a0 = fmaf(c.x, x0, fmaf(c.y, y0, fmaf(c.z, z0, c.w)));
            float a1 = fmaf(c.x, x1, fmaf(c.y, y1, fmaf(c.z, z1, c.w)));
            acc0 += ex2a(a0);
            acc1 += ex2a(a1);
        }
    }

    if (ok0 && ok1) {
        *(float2*)(out + i0) = make_float2(acc0, acc1);   // STG.64, 8B-aligned
    } else if (ok0) {
        out[i0] = acc0;
    }
}

extern "C" void kernel_launch(void* const* d_in, const int* in_sizes, int n_in,
                              void* d_out, int out_size)
{
    const float* lambdas = (const float*)d_in[0];
    const float* kappas  = (const float*)d_in[1];
    const float* thetas  = (const float*)d_in[2];
    const float* phis    = (const float*)d_in[3];
    const float* wi      = (const float*)d_in[4];
    float* out = (float*)d_out;

    int N = in_sizes[0];
    int S = in_sizes[4] / 3;

    int blocks = (S + DIRS_PER_BLOCK - 1) / DIRS_PER_BLOCK;
    vmf_mixture_kernel<<<blocks, BLOCK_THREADS>>>(lambdas, kappas, thetas, phis, wi,
                                                  out, S, N);
}

// round 14
// speedup vs baseline: 1.0136x; 1.0136x over previous
#include <cuda_runtime.h>
#include <math.h>

#define BLOCK_THREADS 128
#define DIRS_PER_THREAD 2
#define DIRS_PER_BLOCK (BLOCK_THREADS * DIRS_PER_THREAD)
#define MAX_COMP 64

__device__ __forceinline__ float ex2a(float x) {
    float r; asm("ex2.approx.ftz.f32 %0, %1;" : "=f"(r) : "f"(x)); return r;
}

__global__ void __launch_bounds__(BLOCK_THREADS, 14)
vmf_mixture_kernel(const float* __restrict__ lambdas,
                   const float* __restrict__ kappas,
                   const float* __restrict__ thetas,
                   const float* __restrict__ phis,
                   const float* __restrict__ wi,
                   float* __restrict__ out,
                   int S, int N)
{
    // per component: {ax, ay, az, b} with a = kappa*log2e folded into mu,
    // b = log2(lambda*norm) - a  (weight folded into the exponent)
    __shared__ float4 sC[MAX_COMP];

    int t = threadIdx.x;
    if (t < N) {
        float kappa = kappas[t];
        float lam   = lambdas[t];
        float th    = thetas[t];
        float ph    = phis[t];

        float st = sinf(th), ct = cosf(th);
        float sp = sinf(ph), cp = cosf(ph);

        float k = fmaxf(kappa, 1e-8f);
        float norm = (kappa < 1e-5f)
                   ? 0.07957747154594767f                       // 1/(4pi)
                   : k * 0.15915494309189535f / (1.0f - expf(-2.0f * k));
        float c = lam * norm;                                   // > 0 always

        const float LOG2E = 1.4426950408889634f;
        float a = kappa * LOG2E;
        float b = log2f(c) - a;
        sC[t] = make_float4(a * (st * cp), a * (st * sp), a * ct, b);
    }
    __syncthreads();

    // contiguous pair of directions per thread: 3x LDG.64 in, 1x STG.64 out
    int gid = blockIdx.x * BLOCK_THREADS + t;          // pair index
    int i0 = 2 * gid;
    int i1 = i0 + 1;
    bool ok0 = (i0 < S);
    bool ok1 = (i1 < S);
    long long off = ok0 ? (long long)3 * i0 : 0;       // 6 consecutive floats

    const float2* wv = (const float2*)(wi + off);      // 8B-aligned (24B stride)
    float2 p0 = wv[0];                                 // x0 y0
    float2 p1 = wv[1];                                 // z0 x1
    float2 p2 = wv[2];                                 // y1 z1
    float x0 = p0.x, y0 = p0.y, z0 = p1.x;
    float x1 = p1.y, y1 = p2.x, z1 = p2.y;

    float acc0 = 0.0f, acc1 = 0.0f;

    if (N == MAX_COMP) {
        // compile-time trip count: fully unrolled, globally scheduled
        #pragma unroll
        for (int n = 0; n < MAX_COMP; n++) {
            float4 c = sC[n];
            float a0 = fmaf(c.x, x0, fmaf(c.y, y0, fmaf(c.z, z0, c.w)));
            float a1 = fmaf(c.x, x1, fmaf(c.y, y1, fmaf(c.z, z1, c.w)));
            acc0 += ex2a(a0);
            acc1 += ex2a(a1);
        }
    } else {
        #pragma unroll 4
        for (int n = 0; n < N; n++) {
            float4 c = sC[n];
            float a0 = fmaf(c.x, x0, fmaf(c.y, y0, fmaf(c.z, z0, c.w)));
            float a1 = fmaf(c.x, x1, fmaf(c.y, y1, fmaf(c.z, z1, c.w)));
            acc0 += ex2a(a0);
            acc1 += ex2a(a1);
        }
    }

    if (ok0 && ok1) {
        *(float2*)(out + i0) = make_float2(acc0, acc1);   // STG.64, 8B-aligned
    } else if (ok0) {
        out[i0] = acc0;
    }
}

extern "C" void kernel_launch(void* const* d_in, const int* in_sizes, int n_in,
                              void* d_out, int out_size)
{
    const float* lambdas = (const float*)d_in[0];
    const float* kappas  = (const float*)d_in[1];
    const float* thetas  = (const float*)d_in[2];
    const float* phis    = (const float*)d_in[3];
    const float* wi      = (const float*)d_in[4];
    float* out = (float*)d_out;

    int N = in_sizes[0];
    int S = in_sizes[4] / 3;

    int blocks = (S + DIRS_PER_BLOCK - 1) / DIRS_PER_BLOCK;
    vmf_mixture_kernel<<<blocks, BLOCK_THREADS>>>(lambdas, kappas, thetas, phis, wi,
                                                  out, S, N);
}